// round 10
// baseline (speedup 1.0000x reference)
#include <cuda_runtime.h>
#include <cuda_fp16.h>
#include <cuda_bf16.h>

#define MAXN 100000
#define MAXE 1600000
#define F 64

// ---------------- scratch (static device globals; no allocation) -------------
__device__ int      d_is64;                // 1 if edge_index is int64
__device__ int      d_counts[MAXN];        // degree counts (incl. self loop)
__device__ int      d_rowptr[MAXN + 1];    // CSR row pointers (by destination)
__device__ int      d_cursor[MAXN];        // scatter cursors
__device__ float    d_dinv[MAXN];          // deg^-1/2
__device__ int      d_blocksums[512];      // scanA inclusive block sums
__device__ float2   d_edges[MAXE + MAXN];  // packed {src_as_float_bits, norm}
__device__ unsigned d_xh[MAXN * 32];       // x in fp16 (32 half2 words/node)
__device__ unsigned d_ax[MAXN * 32];       // aggregation output (fp16)
__device__ unsigned d_gh[MAXN * 32];       // layer-1 activation (fp16)

__device__ __forceinline__ unsigned h2_bits(__half2 h) {
    union { __half2 h; unsigned u; } cvt;
    cvt.h = h;
    return cvt.u;
}

// ---------------- edge index accessors ---------------------------------------
__device__ __forceinline__ int edge_at(const void* ei, long long idx) {
    if (d_is64) return (int)((const long long*)ei)[idx];
    return ((const int*)ei)[idx];
}

__device__ __forceinline__ int2 edge_pair(const void* ei, long long halfidx) {
    if (d_is64) {
        longlong2 v = ((const longlong2*)ei)[halfidx];
        return make_int2((int)v.x, (int)v.y);
    }
    return ((const int2*)ei)[halfidx];
}

// ---------------- k0: dtype detect + init counts ------------------------------
__global__ void k_init(const unsigned int* __restrict__ p, int n) {
    int i = blockIdx.x * blockDim.x + threadIdx.x;
    if (i < n) d_counts[i] = 1;  // self loop
    if (blockIdx.x == 0 && threadIdx.x < 64) {
        bool allz = true;
        for (int k = threadIdx.x * 2 + 1; k < 256; k += 128) {
            if (p[k] != 0u) allz = false;
        }
        unsigned int m = __ballot_sync(0xffffffffu, allz);
        if (threadIdx.x == 0) d_is64 = (m == 0xffffffffu) ? 1 : 0;
    }
}

// fused: histogram of destinations (blocks [0,nbH)) + x fp32->fp16 (rest)
__global__ void k_histxh(const void* __restrict__ ei, const float* __restrict__ x,
                         int E, int nbH, int n16) {
    int b = blockIdx.x;
    if (b < nbH) {
        int e = (b * 256 + threadIdx.x) * 2;
        if (e + 1 < E) {
            int2 c = edge_pair(ei, ((long long)E + e) >> 1);
            atomicAdd(&d_counts[c.x], 1);
            atomicAdd(&d_counts[c.y], 1);
        } else if (e < E) {
            atomicAdd(&d_counts[edge_at(ei, (long long)E + e)], 1);
        }
    } else {
        int i = (b - nbH) * 256 + threadIdx.x;
        if (i < n16) {
            float4 v = ((const float4*)x)[i];
            uint2 w;
            w.x = h2_bits(__floats2half2_rn(v.x, v.y));
            w.y = h2_bits(__floats2half2_rn(v.z, v.w));
            ((uint2*)d_xh)[i] = w;
        }
    }
}

// scanA: block-local exclusive scan + fused dinv
__global__ void k_scanA(int n) {  // 512 threads/block
    int i = blockIdx.x * 512 + threadIdx.x;
    int lane = threadIdx.x & 31;
    int v = (i < n) ? d_counts[i] : 0;
    if (i < n) d_dinv[i] = rsqrtf((float)v);
    int x = v;
    #pragma unroll
    for (int d = 1; d < 32; d <<= 1) {
        int y = __shfl_up_sync(0xffffffffu, x, d);
        if (lane >= d) x += y;
    }
    __shared__ int ws[16];
    if (lane == 31) ws[threadIdx.x >> 5] = x;
    __syncthreads();
    if (threadIdx.x < 16) {
        int z = ws[threadIdx.x];
        #pragma unroll
        for (int d = 1; d < 16; d <<= 1) {
            int y = __shfl_up_sync(0xffffu, z, d);
            if ((int)threadIdx.x >= d) z += y;
        }
        ws[threadIdx.x] = z;
    }
    __syncthreads();
    int off = (threadIdx.x >= 32) ? ws[(threadIdx.x >> 5) - 1] : 0;
    int incl = x + off;
    if (i < n) d_rowptr[i] = incl - v;
    if (threadIdx.x == 511) d_blocksums[blockIdx.x] = incl;
}

// scanC: re-scan block sums per block, apply offsets
__global__ void k_scanC(int n, int total, int nb) {
    __shared__ int sa[256], sb[256];
    int t = threadIdx.x;
    sa[t] = (t < nb) ? d_blocksums[t] : 0;
    __syncthreads();
    int* src = sa;
    int* dst = sb;
    #pragma unroll
    for (int d = 1; d < 256; d <<= 1) {
        int v = src[t];
        if (t >= d) v += src[t - d];
        dst[t] = v;
        __syncthreads();
        int* tmp = src; src = dst; dst = tmp;
    }
    int i = blockIdx.x * 256 + t;
    if (i < n) {
        int b = i >> 9;
        int off = b ? src[b - 1] : 0;
        int r = d_rowptr[i] + off;
        d_rowptr[i] = r;
        d_cursor[i] = r;
    }
    if (i == 0) d_rowptr[n] = total;
}

// scatter: 2 edges per thread (vector index loads), then self loops
__global__ void k_scatter(const void* __restrict__ ei, int E, int n) {
    int idx = blockIdx.x * blockDim.x + threadIdx.x;
    int Eh = (E + 1) >> 1;
    if (idx < Eh) {
        int e = idx * 2;
        if (e + 1 < E) {
            int2 r = edge_pair(ei, (long long)e >> 1);
            int2 c = edge_pair(ei, ((long long)E + e) >> 1);
            float nm0 = d_dinv[r.x] * d_dinv[c.x];
            float nm1 = d_dinv[r.y] * d_dinv[c.y];
            int p0 = atomicAdd(&d_cursor[c.x], 1);
            d_edges[p0] = make_float2(__int_as_float(r.x), nm0);
            int p1 = atomicAdd(&d_cursor[c.y], 1);
            d_edges[p1] = make_float2(__int_as_float(r.y), nm1);
        } else {
            int r = edge_at(ei, e);
            int c = edge_at(ei, (long long)E + e);
            float nm = d_dinv[r] * d_dinv[c];
            int pos = atomicAdd(&d_cursor[c], 1);
            d_edges[pos] = make_float2(__int_as_float(r), nm);
        }
    } else if (idx < Eh + n) {
        int i = idx - Eh;
        float di = d_dinv[i];
        int pos = atomicAdd(&d_cursor[i], 1);
        d_edges[pos] = make_float2(__int_as_float(i), di * di);
    }
}

// ---------------- aggregation: d_ax[c] = sum_{e: col=c} norm_e * S[src_e] -----
// warp per node, HALF-WARP per edge: 16 lanes x uint2 (8B) cover one 128B fp16
// row; 2 edges per gather instruction, 4-unrolled -> 8 edges/lines in flight.
// fp32 accumulate, cross-half-warp SHFL reduce, fp16 out.
template <bool SECOND>
__global__ void k_agg(int n) {
    int gwarp = (blockIdx.x * blockDim.x + threadIdx.x) >> 5;
    if (gwarp >= n) return;
    int lane = threadIdx.x & 31;
    int hw = lane >> 4;   // which edge of the pair
    int hl = lane & 15;   // 8B chunk within the row (features 4hl..4hl+3)
    int s = d_rowptr[gwarp];
    int e = d_rowptr[gwarp + 1];
    const uint2* X = (const uint2*)(SECOND ? d_gh : d_xh);
    float a0 = 0.f, a1 = 0.f, a2 = 0.f, a3 = 0.f;

    #define GATH(m) do {                                                     \
        uint2 g = X[__float_as_int((m).x) * 16 + hl];                        \
        float2 f0 = __half22float2(*(const __half2*)&g.x);                   \
        float2 f1 = __half22float2(*(const __half2*)&g.y);                   \
        a0 += (m).y * f0.x; a1 += (m).y * f0.y;                              \
        a2 += (m).y * f1.x; a3 += (m).y * f1.y;                              \
    } while (0)

    int j = s;
    for (; j + 7 < e; j += 8) {
        float2 m0 = d_edges[j + hw];
        float2 m1 = d_edges[j + 2 + hw];
        float2 m2 = d_edges[j + 4 + hw];
        float2 m3 = d_edges[j + 6 + hw];
        GATH(m0); GATH(m1); GATH(m2); GATH(m3);
    }
    for (; j + 1 < e; j += 2) {
        float2 m = d_edges[j + hw];
        GATH(m);
    }
    if (j < e && hw == 0) {
        float2 m = d_edges[j];
        GATH(m);
    }
    #undef GATH

    a0 += __shfl_xor_sync(0xffffffffu, a0, 16);
    a1 += __shfl_xor_sync(0xffffffffu, a1, 16);
    a2 += __shfl_xor_sync(0xffffffffu, a2, 16);
    a3 += __shfl_xor_sync(0xffffffffu, a3, 16);

    if (hw == 0) {
        uint2 w;
        w.x = h2_bits(__floats2half2_rn(a0, a1));
        w.y = h2_bits(__floats2half2_rn(a2, a3));
        ((uint2*)d_ax)[gwarp * 16 + hl] = w;
    }
}

// ---------------- GEMM via tensor cores (HMMA m16n8k16) ----------------------
// reads d_ax (fp16), computes d_ax@W + b; RELU=true -> relu, fp16 to d_gh;
// RELU=false -> fp32 to OUT. 256 threads, 128 nodes/block; warp = 16x64 tile.
#define XS_PITCH 72
template <bool RELU>
__global__ __launch_bounds__(256) void k_gemm(const float* __restrict__ W,
                                              const float* __restrict__ bias,
                                              float* __restrict__ OUT, int n) {
    __shared__ __half Xs[128 * XS_PITCH];  // 18 KB
    __shared__ __half Wt[64 * XS_PITCH];   // 9 KB, Wt[f][k] = W[k][f]
    int t = threadIdx.x;
    int base = blockIdx.x * 128;

    // X tile fill via cp.async: 128 nodes * 8 uint4 = 1024, 4 per thread
    for (int i = t; i < 1024; i += 256) {
        int node = i >> 3, q = i & 7;
        void* dst = &Xs[node * XS_PITCH + q * 8];
        if (base + node < n) {
            unsigned ds = (unsigned)__cvta_generic_to_shared(dst);
            const uint4* src = (const uint4*)&d_ax[(base + node) * 32 + q * 4];
            asm volatile("cp.async.ca.shared.global [%0], [%1], 16;"
                         :: "r"(ds), "l"(src));
        } else {
            *(uint4*)dst = make_uint4(0, 0, 0, 0);
        }
    }
    asm volatile("cp.async.commit_group;");
    // W[64,64] fp32 -> Wt fp16 transposed (overlaps with cp.async)
    for (int i = t; i < 4096; i += 256) {
        int k = i >> 6, f = i & 63;
        Wt[f * XS_PITCH + k] = __float2half(W[k * 64 + f]);
    }
    asm volatile("cp.async.wait_group 0;");
    __syncthreads();

    int warp = t >> 5, lane = t & 31;
    int gid = lane >> 2, tig = lane & 3;
    int mbase = warp * 16;

    float c[8][4];
    #pragma unroll
    for (int nt = 0; nt < 8; nt++)
        #pragma unroll
        for (int q = 0; q < 4; q++) c[nt][q] = 0.f;

    #pragma unroll
    for (int kt = 0; kt < 4; kt++) {
        int k0 = kt * 16 + 2 * tig;
        unsigned a0 = *(const unsigned*)&Xs[(mbase + gid) * XS_PITCH + k0];
        unsigned a1 = *(const unsigned*)&Xs[(mbase + gid + 8) * XS_PITCH + k0];
        unsigned a2 = *(const unsigned*)&Xs[(mbase + gid) * XS_PITCH + k0 + 8];
        unsigned a3 = *(const unsigned*)&Xs[(mbase + gid + 8) * XS_PITCH + k0 + 8];
        #pragma unroll
        for (int nt = 0; nt < 8; nt++) {
            unsigned b0 = *(const unsigned*)&Wt[(nt * 8 + gid) * XS_PITCH + k0];
            unsigned b1 = *(const unsigned*)&Wt[(nt * 8 + gid) * XS_PITCH + k0 + 8];
            asm volatile(
                "mma.sync.aligned.m16n8k16.row.col.f32.f16.f16.f32 "
                "{%0,%1,%2,%3}, {%4,%5,%6,%7}, {%8,%9}, {%0,%1,%2,%3};"
                : "+f"(c[nt][0]), "+f"(c[nt][1]), "+f"(c[nt][2]), "+f"(c[nt][3])
                : "r"(a0), "r"(a1), "r"(a2), "r"(a3), "r"(b0), "r"(b1));
        }
    }

    // epilogue: +bias (, relu); c0,c1 = row gid, c2,c3 = row gid+8
    int node = base + mbase + gid;
    #pragma unroll
    for (int nt = 0; nt < 8; nt++) {
        int word = nt * 4 + tig;  // half2/float2 word = features {2w, 2w+1}
        float2 bb = __ldg(&((const float2*)bias)[word]);
        float v0 = c[nt][0] + bb.x, v1 = c[nt][1] + bb.y;
        float v2 = c[nt][2] + bb.x, v3 = c[nt][3] + bb.y;
        if (RELU) {
            v0 = fmaxf(v0, 0.f); v1 = fmaxf(v1, 0.f);
            v2 = fmaxf(v2, 0.f); v3 = fmaxf(v3, 0.f);
            if (node < n)
                d_gh[node * 32 + word] = h2_bits(__floats2half2_rn(v0, v1));
            if (node + 8 < n)
                d_gh[(node + 8) * 32 + word] = h2_bits(__floats2half2_rn(v2, v3));
        } else {
            if (node < n)
                ((float2*)OUT)[node * 32 + word] = make_float2(v0, v1);
            if (node + 8 < n)
                ((float2*)OUT)[(node + 8) * 32 + word] = make_float2(v2, v3);
        }
    }
}

// ---------------- launch -----------------------------------------------------
extern "C" void kernel_launch(void* const* d_in, const int* in_sizes, int n_in,
                              void* d_out, int out_size) {
    const float* x = (const float*)d_in[0];
    const void* ei = d_in[1];
    const float* W1 = (const float*)d_in[2];
    const float* b1 = (const float*)d_in[3];
    const float* W2 = (const float*)d_in[4];
    const float* b2 = (const float*)d_in[5];
    float* out = (float*)d_out;

    int N = in_sizes[0] / F;          // 100000
    int E = in_sizes[1] / 2;          // 1600000
    int nbA = (N + 511) / 512;        // 196
    int Eh = (E + 1) / 2;
    int nbH = (Eh + 255) / 256;       // hist blocks (2 edges/thread)
    int nbX = (N * 16 + 255) / 256;   // xh blocks

    // graph build (+ fused x->fp16)
    k_init<<<(N + 255) / 256, 256>>>((const unsigned int*)ei, N);
    k_histxh<<<nbH + nbX, 256>>>(ei, x, E, nbH, N * 16);
    k_scanA<<<nbA, 512>>>(N);
    k_scanC<<<(N + 255) / 256, 256>>>(N, E + N, nbA);
    k_scatter<<<(Eh + N + 255) / 256, 256>>>(ei, E, N);

    // layer 1: AX = agg(xh); gh = relu(AX@W1 + b1)
    k_agg<false><<<(N * 32 + 255) / 256, 256>>>(N);
    k_gemm<true><<<(N + 127) / 128, 256>>>(W1, b1, out /*unused*/, N);

    // layer 2: Ag = agg(gh); out = Ag@W2 + b2
    k_agg<true><<<(N * 32 + 255) / 256, 256>>>(N);
    k_gemm<false><<<(N + 127) / 128, 256>>>(W2, b2, out, N);
}

// round 11
// speedup vs baseline: 1.0021x; 1.0021x over previous
#include <cuda_runtime.h>
#include <cuda_fp16.h>
#include <cuda_bf16.h>

#define MAXN 100000
#define MAXE 1600000
#define F 64

// ---------------- scratch (static device globals; no allocation) -------------
__device__ int      d_is64;                // 1 if edge_index is int64
__device__ int      d_counts[MAXN];        // degree counts (incl. self loop)
__device__ int      d_rowptr[MAXN + 1];    // CSR row pointers (by destination)
__device__ int      d_cursor[MAXN];        // scatter cursors
__device__ float    d_dinv[MAXN];          // deg^-1/2
__device__ unsigned long long d_scanstate[512];  // lookback: {status:2,val:62}
__device__ unsigned d_ticket;              // block ordering ticket
__device__ float2   d_edges[MAXE + MAXN];  // packed {src_as_float_bits, norm}
__device__ unsigned d_xh[MAXN * 32];       // x in fp16 (32 half2 words/node)
__device__ unsigned d_ax[MAXN * 32];       // aggregation output (fp16)
__device__ unsigned d_gh[MAXN * 32];       // layer-1 activation (fp16)

__device__ __forceinline__ unsigned h2_bits(__half2 h) {
    union { __half2 h; unsigned u; } cvt;
    cvt.h = h;
    return cvt.u;
}

// ---------------- edge index accessors ---------------------------------------
__device__ __forceinline__ int edge_at(const void* ei, long long idx) {
    if (d_is64) return (int)((const long long*)ei)[idx];
    return ((const int*)ei)[idx];
}

__device__ __forceinline__ int2 edge_pair(const void* ei, long long halfidx) {
    if (d_is64) {
        longlong2 v = ((const longlong2*)ei)[halfidx];
        return make_int2((int)v.x, (int)v.y);
    }
    return ((const int2*)ei)[halfidx];
}

// ---------------- k0: dtype detect + init counts + zero scan state -----------
__global__ void k_init(const unsigned int* __restrict__ p, int n) {
    int i = blockIdx.x * blockDim.x + threadIdx.x;
    if (i < n) d_counts[i] = 1;  // self loop
    if (i < 512) d_scanstate[i] = 0ull;
    if (i == 0) d_ticket = 0u;
    if (blockIdx.x == 0 && threadIdx.x < 64) {
        bool allz = true;
        for (int k = threadIdx.x * 2 + 1; k < 256; k += 128) {
            if (p[k] != 0u) allz = false;
        }
        unsigned int m = __ballot_sync(0xffffffffu, allz);
        if (threadIdx.x == 0) d_is64 = (m == 0xffffffffu) ? 1 : 0;
    }
}

// fused: histogram of destinations (blocks [0,nbH)) + x fp32->fp16 (rest)
__global__ void k_histxh(const void* __restrict__ ei, const float* __restrict__ x,
                         int E, int nbH, int n16) {
    int b = blockIdx.x;
    if (b < nbH) {
        int e = (b * 256 + threadIdx.x) * 2;
        if (e + 1 < E) {
            int2 c = edge_pair(ei, ((long long)E + e) >> 1);
            atomicAdd(&d_counts[c.x], 1);
            atomicAdd(&d_counts[c.y], 1);
        } else if (e < E) {
            atomicAdd(&d_counts[edge_at(ei, (long long)E + e)], 1);
        }
    } else {
        int i = (b - nbH) * 256 + threadIdx.x;
        if (i < n16) {
            float4 v = ((const float4*)x)[i];
            uint2 w;
            w.x = h2_bits(__floats2half2_rn(v.x, v.y));
            w.y = h2_bits(__floats2half2_rn(v.z, v.w));
            ((uint2*)d_xh)[i] = w;
        }
    }
}

// single-pass scan (decoupled lookback) + fused dinv; replaces scanA+scanC.
__global__ void k_scan(int n, int nb, int total) {  // 512 threads/block
    __shared__ unsigned sbid;
    __shared__ int srun;
    __shared__ int ws[16];
    if (threadIdx.x == 0) sbid = atomicAdd(&d_ticket, 1u);
    __syncthreads();
    int bid = (int)sbid;
    int i = bid * 512 + threadIdx.x;
    int lane = threadIdx.x & 31;
    int v = (i < n) ? d_counts[i] : 0;
    if (i < n) d_dinv[i] = rsqrtf((float)v);
    int x = v;
    #pragma unroll
    for (int d = 1; d < 32; d <<= 1) {
        int y = __shfl_up_sync(0xffffffffu, x, d);
        if (lane >= d) x += y;
    }
    if (lane == 31) ws[threadIdx.x >> 5] = x;
    __syncthreads();
    if (threadIdx.x < 16) {
        int z = ws[threadIdx.x];
        #pragma unroll
        for (int d = 1; d < 16; d <<= 1) {
            int y = __shfl_up_sync(0xffffu, z, d);
            if ((int)threadIdx.x >= d) z += y;
        }
        ws[threadIdx.x] = z;
    }
    __syncthreads();
    int off = (threadIdx.x >= 32) ? ws[(threadIdx.x >> 5) - 1] : 0;
    int incl = x + off;  // block-local inclusive scan of v

    if (threadIdx.x == 511) {
        int btotal = incl;
        if (bid == 0) {
            atomicExch(&d_scanstate[0],
                       (2ull << 62) | (unsigned long long)(unsigned)btotal);
            srun = 0;
        } else {
            atomicExch(&d_scanstate[bid],
                       (1ull << 62) | (unsigned long long)(unsigned)btotal);
            int running = 0;
            int j = bid - 1;
            while (true) {
                unsigned long long s;
                do {
                    s = *(volatile unsigned long long*)&d_scanstate[j];
                } while ((s >> 62) == 0ull);
                int val = (int)(s & 0xffffffffull);
                running += val;
                if ((s >> 62) == 2ull) break;
                j--;
            }
            atomicExch(&d_scanstate[bid],
                       (2ull << 62) | (unsigned long long)(unsigned)(running + btotal));
            srun = running;
        }
    }
    __syncthreads();
    int run = srun;
    if (i < n) {
        int r = incl - v + run;
        d_rowptr[i] = r;
        d_cursor[i] = r;
    }
    if (i == 0) d_rowptr[n] = total;
}

// scatter: 2 edges per thread (vector index loads), then self loops
__global__ void k_scatter(const void* __restrict__ ei, int E, int n) {
    int idx = blockIdx.x * blockDim.x + threadIdx.x;
    int Eh = (E + 1) >> 1;
    if (idx < Eh) {
        int e = idx * 2;
        if (e + 1 < E) {
            int2 r = edge_pair(ei, (long long)e >> 1);
            int2 c = edge_pair(ei, ((long long)E + e) >> 1);
            float nm0 = d_dinv[r.x] * d_dinv[c.x];
            float nm1 = d_dinv[r.y] * d_dinv[c.y];
            int p0 = atomicAdd(&d_cursor[c.x], 1);
            d_edges[p0] = make_float2(__int_as_float(r.x), nm0);
            int p1 = atomicAdd(&d_cursor[c.y], 1);
            d_edges[p1] = make_float2(__int_as_float(r.y), nm1);
        } else {
            int r = edge_at(ei, e);
            int c = edge_at(ei, (long long)E + e);
            float nm = d_dinv[r] * d_dinv[c];
            int pos = atomicAdd(&d_cursor[c], 1);
            d_edges[pos] = make_float2(__int_as_float(r), nm);
        }
    } else if (idx < Eh + n) {
        int i = idx - Eh;
        float di = d_dinv[i];
        int pos = atomicAdd(&d_cursor[i], 1);
        d_edges[pos] = make_float2(__int_as_float(i), di * di);
    }
}

// ---------------- aggregation: d_ax[c] = sum_{e: col=c} norm_e * S[src_e] -----
// warp per node; S fp16 (half2/lane -> 128B gather/edge), fp32 accum, fp16 out.
// (round-9 proven form)
template <bool SECOND>
__global__ void k_agg(int n) {
    int gwarp = (blockIdx.x * blockDim.x + threadIdx.x) >> 5;
    if (gwarp >= n) return;
    int lane = threadIdx.x & 31;
    int s = d_rowptr[gwarp];
    int e = d_rowptr[gwarp + 1];
    const __half2* H2 = (const __half2*)(SECOND ? d_gh : d_xh);
    float ax = 0.f, ay = 0.f;
    int j = s;
    for (; j + 3 < e; j += 4) {
        float2 e0 = d_edges[j];
        float2 e1 = d_edges[j + 1];
        float2 e2 = d_edges[j + 2];
        float2 e3 = d_edges[j + 3];
        float2 h0 = __half22float2(H2[__float_as_int(e0.x) * 32 + lane]);
        float2 h1 = __half22float2(H2[__float_as_int(e1.x) * 32 + lane]);
        float2 h2 = __half22float2(H2[__float_as_int(e2.x) * 32 + lane]);
        float2 h3 = __half22float2(H2[__float_as_int(e3.x) * 32 + lane]);
        ax += e0.y * h0.x + e1.y * h1.x + e2.y * h2.x + e3.y * h3.x;
        ay += e0.y * h0.y + e1.y * h1.y + e2.y * h2.y + e3.y * h3.y;
    }
    for (; j < e; j++) {
        float2 e0 = d_edges[j];
        float2 h0 = __half22float2(H2[__float_as_int(e0.x) * 32 + lane]);
        ax += e0.y * h0.x;
        ay += e0.y * h0.y;
    }
    d_ax[gwarp * 32 + lane] = h2_bits(__floats2half2_rn(ax, ay));
}

// ---------------- GEMM via tensor cores (HMMA m16n8k16) ----------------------
// reads d_ax (fp16), computes d_ax@W + b; RELU=true -> relu, fp16 to d_gh;
// RELU=false -> fp32 to OUT. 256 threads, 128 nodes/block; warp = 16x64 tile.
#define XS_PITCH 72
template <bool RELU>
__global__ __launch_bounds__(256) void k_gemm(const float* __restrict__ W,
                                              const float* __restrict__ bias,
                                              float* __restrict__ OUT, int n) {
    __shared__ __half Xs[128 * XS_PITCH];  // 18 KB
    __shared__ __half Wt[64 * XS_PITCH];   // 9 KB, Wt[f][k] = W[k][f]
    int t = threadIdx.x;
    int base = blockIdx.x * 128;

    // X tile fill via cp.async: 128 nodes * 8 uint4 = 1024, 4 per thread
    for (int i = t; i < 1024; i += 256) {
        int node = i >> 3, q = i & 7;
        void* dst = &Xs[node * XS_PITCH + q * 8];
        if (base + node < n) {
            unsigned ds = (unsigned)__cvta_generic_to_shared(dst);
            const uint4* src = (const uint4*)&d_ax[(base + node) * 32 + q * 4];
            asm volatile("cp.async.ca.shared.global [%0], [%1], 16;"
                         :: "r"(ds), "l"(src));
        } else {
            *(uint4*)dst = make_uint4(0, 0, 0, 0);
        }
    }
    asm volatile("cp.async.commit_group;");
    // W[64,64] fp32 -> Wt fp16 transposed (overlaps with cp.async)
    for (int i = t; i < 4096; i += 256) {
        int k = i >> 6, f = i & 63;
        Wt[f * XS_PITCH + k] = __float2half(W[k * 64 + f]);
    }
    asm volatile("cp.async.wait_group 0;");
    __syncthreads();

    int warp = t >> 5, lane = t & 31;
    int gid = lane >> 2, tig = lane & 3;
    int mbase = warp * 16;

    float c[8][4];
    #pragma unroll
    for (int nt = 0; nt < 8; nt++)
        #pragma unroll
        for (int q = 0; q < 4; q++) c[nt][q] = 0.f;

    #pragma unroll
    for (int kt = 0; kt < 4; kt++) {
        int k0 = kt * 16 + 2 * tig;
        unsigned a0 = *(const unsigned*)&Xs[(mbase + gid) * XS_PITCH + k0];
        unsigned a1 = *(const unsigned*)&Xs[(mbase + gid + 8) * XS_PITCH + k0];
        unsigned a2 = *(const unsigned*)&Xs[(mbase + gid) * XS_PITCH + k0 + 8];
        unsigned a3 = *(const unsigned*)&Xs[(mbase + gid + 8) * XS_PITCH + k0 + 8];
        #pragma unroll
        for (int nt = 0; nt < 8; nt++) {
            unsigned b0 = *(const unsigned*)&Wt[(nt * 8 + gid) * XS_PITCH + k0];
            unsigned b1 = *(const unsigned*)&Wt[(nt * 8 + gid) * XS_PITCH + k0 + 8];
            asm volatile(
                "mma.sync.aligned.m16n8k16.row.col.f32.f16.f16.f32 "
                "{%0,%1,%2,%3}, {%4,%5,%6,%7}, {%8,%9}, {%0,%1,%2,%3};"
                : "+f"(c[nt][0]), "+f"(c[nt][1]), "+f"(c[nt][2]), "+f"(c[nt][3])
                : "r"(a0), "r"(a1), "r"(a2), "r"(a3), "r"(b0), "r"(b1));
        }
    }

    // epilogue: +bias (, relu); c0,c1 = row gid, c2,c3 = row gid+8
    int node = base + mbase + gid;
    #pragma unroll
    for (int nt = 0; nt < 8; nt++) {
        int word = nt * 4 + tig;  // half2/float2 word = features {2w, 2w+1}
        float2 bb = __ldg(&((const float2*)bias)[word]);
        float v0 = c[nt][0] + bb.x, v1 = c[nt][1] + bb.y;
        float v2 = c[nt][2] + bb.x, v3 = c[nt][3] + bb.y;
        if (RELU) {
            v0 = fmaxf(v0, 0.f); v1 = fmaxf(v1, 0.f);
            v2 = fmaxf(v2, 0.f); v3 = fmaxf(v3, 0.f);
            if (node < n)
                d_gh[node * 32 + word] = h2_bits(__floats2half2_rn(v0, v1));
            if (node + 8 < n)
                d_gh[(node + 8) * 32 + word] = h2_bits(__floats2half2_rn(v2, v3));
        } else {
            if (node < n)
                ((float2*)OUT)[node * 32 + word] = make_float2(v0, v1);
            if (node + 8 < n)
                ((float2*)OUT)[(node + 8) * 32 + word] = make_float2(v2, v3);
        }
    }
}

// ---------------- launch -----------------------------------------------------
extern "C" void kernel_launch(void* const* d_in, const int* in_sizes, int n_in,
                              void* d_out, int out_size) {
    const float* x = (const float*)d_in[0];
    const void* ei = d_in[1];
    const float* W1 = (const float*)d_in[2];
    const float* b1 = (const float*)d_in[3];
    const float* W2 = (const float*)d_in[4];
    const float* b2 = (const float*)d_in[5];
    float* out = (float*)d_out;

    int N = in_sizes[0] / F;          // 100000
    int E = in_sizes[1] / 2;          // 1600000
    int nbS = (N + 511) / 512;        // 196 scan blocks
    int Eh = (E + 1) / 2;
    int nbH = (Eh + 255) / 256;       // hist blocks (2 edges/thread)
    int nbX = (N * 16 + 255) / 256;   // xh blocks

    // graph build (+ fused x->fp16); k_scatter sits at profiled slot 4
    k_init<<<(N + 255) / 256, 256>>>((const unsigned int*)ei, N);
    k_histxh<<<nbH + nbX, 256>>>(ei, x, E, nbH, N * 16);
    k_scan<<<nbS, 512>>>(N, nbS, E + N);
    k_scatter<<<(Eh + N + 255) / 256, 256>>>(ei, E, N);   // profiled slot

    // layer 1: AX = agg(xh); gh = relu(AX@W1 + b1)
    k_agg<false><<<(N * 32 + 255) / 256, 256>>>(N);
    k_gemm<true><<<(N + 127) / 128, 256>>>(W1, b1, out /*unused*/, N);

    // layer 2: Ag = agg(gh); out = Ag@W2 + b2
    k_agg<true><<<(N * 32 + 255) / 256, 256>>>(N);
    k_gemm<false><<<(N + 127) / 128, 256>>>(W2, b2, out, N);
}

// round 12
// speedup vs baseline: 1.0423x; 1.0401x over previous
#include <cuda_runtime.h>
#include <cuda_fp16.h>
#include <cuda_bf16.h>

#define MAXN 100000
#define MAXE 1600000
#define F 64

// ---------------- scratch (static device globals; no allocation) -------------
__device__ int      d_is64;                // 1 if edge_index is int64
__device__ int      d_counts[MAXN];        // degree counts (incl. self loop)
__device__ int      d_rowptr[MAXN + 1];    // CSR row pointers (by destination)
__device__ int      d_cursor[MAXN];        // scatter cursors
__device__ float    d_dinv[MAXN];          // deg^-1/2
__device__ unsigned long long d_scanstate[512];  // lookback: {status:2,val:62}
__device__ unsigned d_ticket;              // block ordering ticket
__device__ int      d_edgesrc[MAXE + MAXN];// CSR-by-dst: source index per slot
__device__ unsigned d_xh[MAXN * 32];       // dinv-scaled x, fp16 (32 half2/node)
__device__ unsigned d_ax[MAXN * 32];       // aggregation output (fp16)
__device__ unsigned d_gh[MAXN * 32];       // dinv-scaled layer-1 act (fp16)

__device__ __forceinline__ unsigned h2_bits(__half2 h) {
    union { __half2 h; unsigned u; } cvt;
    cvt.h = h;
    return cvt.u;
}

// ---------------- edge index accessors ---------------------------------------
__device__ __forceinline__ int edge_at(const void* ei, long long idx) {
    if (d_is64) return (int)((const long long*)ei)[idx];
    return ((const int*)ei)[idx];
}

__device__ __forceinline__ int2 edge_pair(const void* ei, long long halfidx) {
    if (d_is64) {
        longlong2 v = ((const longlong2*)ei)[halfidx];
        return make_int2((int)v.x, (int)v.y);
    }
    return ((const int2*)ei)[halfidx];
}

// ---------------- k0: dtype detect + init counts + zero scan state -----------
__global__ void k_init(const unsigned int* __restrict__ p, int n) {
    int i = blockIdx.x * blockDim.x + threadIdx.x;
    if (i < n) d_counts[i] = 1;  // self loop
    if (i < 512) d_scanstate[i] = 0ull;
    if (i == 0) d_ticket = 0u;
    if (blockIdx.x == 0 && threadIdx.x < 64) {
        bool allz = true;
        for (int k = threadIdx.x * 2 + 1; k < 256; k += 128) {
            if (p[k] != 0u) allz = false;
        }
        unsigned int m = __ballot_sync(0xffffffffu, allz);
        if (threadIdx.x == 0) d_is64 = (m == 0xffffffffu) ? 1 : 0;
    }
}

// histogram of destinations, 2 edges per thread
__global__ void k_hist(const void* __restrict__ ei, int E) {
    int e = (blockIdx.x * blockDim.x + threadIdx.x) * 2;
    if (e + 1 < E) {
        int2 c = edge_pair(ei, ((long long)E + e) >> 1);
        atomicAdd(&d_counts[c.x], 1);
        atomicAdd(&d_counts[c.y], 1);
    } else if (e < E) {
        atomicAdd(&d_counts[edge_at(ei, (long long)E + e)], 1);
    }
}

// single-pass scan (decoupled lookback) + fused dinv
__global__ void k_scan(int n, int nb, int total) {  // 512 threads/block
    __shared__ unsigned sbid;
    __shared__ int srun;
    __shared__ int ws[16];
    if (threadIdx.x == 0) sbid = atomicAdd(&d_ticket, 1u);
    __syncthreads();
    int bid = (int)sbid;
    int i = bid * 512 + threadIdx.x;
    int lane = threadIdx.x & 31;
    int v = (i < n) ? d_counts[i] : 0;
    if (i < n) d_dinv[i] = rsqrtf((float)v);
    int x = v;
    #pragma unroll
    for (int d = 1; d < 32; d <<= 1) {
        int y = __shfl_up_sync(0xffffffffu, x, d);
        if (lane >= d) x += y;
    }
    if (lane == 31) ws[threadIdx.x >> 5] = x;
    __syncthreads();
    if (threadIdx.x < 16) {
        int z = ws[threadIdx.x];
        #pragma unroll
        for (int d = 1; d < 16; d <<= 1) {
            int y = __shfl_up_sync(0xffffu, z, d);
            if ((int)threadIdx.x >= d) z += y;
        }
        ws[threadIdx.x] = z;
    }
    __syncthreads();
    int off = (threadIdx.x >= 32) ? ws[(threadIdx.x >> 5) - 1] : 0;
    int incl = x + off;

    if (threadIdx.x == 511) {
        int btotal = incl;
        if (bid == 0) {
            atomicExch(&d_scanstate[0],
                       (2ull << 62) | (unsigned long long)(unsigned)btotal);
            srun = 0;
        } else {
            atomicExch(&d_scanstate[bid],
                       (1ull << 62) | (unsigned long long)(unsigned)btotal);
            int running = 0;
            int j = bid - 1;
            while (true) {
                unsigned long long s;
                do {
                    s = *(volatile unsigned long long*)&d_scanstate[j];
                } while ((s >> 62) == 0ull);
                int val = (int)(s & 0xffffffffull);
                running += val;
                if ((s >> 62) == 2ull) break;
                j--;
            }
            atomicExch(&d_scanstate[bid],
                       (2ull << 62) | (unsigned long long)(unsigned)(running + btotal));
            srun = running;
        }
    }
    __syncthreads();
    int run = srun;
    if (i < n) {
        int r = incl - v + run;
        d_rowptr[i] = r;
        d_cursor[i] = r;
    }
    if (i == 0) d_rowptr[n] = total;
}

// fused: scatter src indices (blocks [0,nbSc)) + dinv-scaled x->fp16 (rest).
// Edge record = src only: norm folds as dinv[src] (into rows) * dinv[dst]
// (agg epilogue). Self loop: record src=i; dinv[i]*dinv[i] emerges naturally.
__global__ void k_scatxh(const void* __restrict__ ei, const float* __restrict__ x,
                         int E, int n, int nbSc, int n16) {
    int b = blockIdx.x;
    if (b < nbSc) {
        int idx = b * 256 + threadIdx.x;
        int Eh = (E + 1) >> 1;
        if (idx < Eh) {
            int e = idx * 2;
            if (e + 1 < E) {
                int2 r = edge_pair(ei, (long long)e >> 1);
                int2 c = edge_pair(ei, ((long long)E + e) >> 1);
                int p0 = atomicAdd(&d_cursor[c.x], 1);
                d_edgesrc[p0] = r.x;
                int p1 = atomicAdd(&d_cursor[c.y], 1);
                d_edgesrc[p1] = r.y;
            } else {
                int r = edge_at(ei, e);
                int c = edge_at(ei, (long long)E + e);
                int pos = atomicAdd(&d_cursor[c], 1);
                d_edgesrc[pos] = r;
            }
        } else if (idx < Eh + n) {
            int i = idx - Eh;
            int pos = atomicAdd(&d_cursor[i], 1);
            d_edgesrc[pos] = i;
        }
    } else {
        int i = (b - nbSc) * 256 + threadIdx.x;  // float4 index
        if (i < n16) {
            float di = d_dinv[i >> 4];
            float4 v = ((const float4*)x)[i];
            uint2 w;
            w.x = h2_bits(__floats2half2_rn(di * v.x, di * v.y));
            w.y = h2_bits(__floats2half2_rn(di * v.z, di * v.w));
            ((uint2*)d_xh)[i] = w;
        }
    }
}

// ---------------- aggregation: d_ax[c] = dinv[c] * sum_{e->c} S[src_e] -------
// warp per node; S fp16 dinv-scaled rows (half2/lane), fp32 accum, fp16 out.
template <bool SECOND>
__global__ void k_agg(int n) {
    int gwarp = (blockIdx.x * blockDim.x + threadIdx.x) >> 5;
    if (gwarp >= n) return;
    int lane = threadIdx.x & 31;
    int s = d_rowptr[gwarp];
    int e = d_rowptr[gwarp + 1];
    const __half2* H2 = (const __half2*)(SECOND ? d_gh : d_xh);
    float ax = 0.f, ay = 0.f;
    int j = s;
    for (; j + 3 < e; j += 4) {
        int s0 = d_edgesrc[j];
        int s1 = d_edgesrc[j + 1];
        int s2 = d_edgesrc[j + 2];
        int s3 = d_edgesrc[j + 3];
        float2 h0 = __half22float2(H2[s0 * 32 + lane]);
        float2 h1 = __half22float2(H2[s1 * 32 + lane]);
        float2 h2 = __half22float2(H2[s2 * 32 + lane]);
        float2 h3 = __half22float2(H2[s3 * 32 + lane]);
        ax += h0.x + h1.x + h2.x + h3.x;
        ay += h0.y + h1.y + h2.y + h3.y;
    }
    for (; j < e; j++) {
        float2 h0 = __half22float2(H2[d_edgesrc[j] * 32 + lane]);
        ax += h0.x;
        ay += h0.y;
    }
    float di = d_dinv[gwarp];
    d_ax[gwarp * 32 + lane] = h2_bits(__floats2half2_rn(di * ax, di * ay));
}

// ---------------- GEMM via tensor cores (HMMA m16n8k16) ----------------------
// reads d_ax (fp16), computes d_ax@W + b; RELU=true -> dinv*relu, fp16 to
// d_gh; RELU=false -> fp32 to OUT. 256 threads, 128 nodes/block.
#define XS_PITCH 72
template <bool RELU>
__global__ __launch_bounds__(256) void k_gemm(const float* __restrict__ W,
                                              const float* __restrict__ bias,
                                              float* __restrict__ OUT, int n) {
    __shared__ __half Xs[128 * XS_PITCH];  // 18 KB
    __shared__ __half Wt[64 * XS_PITCH];   // 9 KB, Wt[f][k] = W[k][f]
    int t = threadIdx.x;
    int base = blockIdx.x * 128;

    // X tile fill via cp.async: 128 nodes * 8 uint4 = 1024, 4 per thread
    for (int i = t; i < 1024; i += 256) {
        int node = i >> 3, q = i & 7;
        void* dst = &Xs[node * XS_PITCH + q * 8];
        if (base + node < n) {
            unsigned ds = (unsigned)__cvta_generic_to_shared(dst);
            const uint4* src = (const uint4*)&d_ax[(base + node) * 32 + q * 4];
            asm volatile("cp.async.ca.shared.global [%0], [%1], 16;"
                         :: "r"(ds), "l"(src));
        } else {
            *(uint4*)dst = make_uint4(0, 0, 0, 0);
        }
    }
    asm volatile("cp.async.commit_group;");
    // W[64,64] fp32 -> Wt fp16 transposed (overlaps with cp.async)
    for (int i = t; i < 4096; i += 256) {
        int k = i >> 6, f = i & 63;
        Wt[f * XS_PITCH + k] = __float2half(W[k * 64 + f]);
    }
    asm volatile("cp.async.wait_group 0;");
    __syncthreads();

    int warp = t >> 5, lane = t & 31;
    int gid = lane >> 2, tig = lane & 3;
    int mbase = warp * 16;

    float c[8][4];
    #pragma unroll
    for (int nt = 0; nt < 8; nt++)
        #pragma unroll
        for (int q = 0; q < 4; q++) c[nt][q] = 0.f;

    #pragma unroll
    for (int kt = 0; kt < 4; kt++) {
        int k0 = kt * 16 + 2 * tig;
        unsigned a0 = *(const unsigned*)&Xs[(mbase + gid) * XS_PITCH + k0];
        unsigned a1 = *(const unsigned*)&Xs[(mbase + gid + 8) * XS_PITCH + k0];
        unsigned a2 = *(const unsigned*)&Xs[(mbase + gid) * XS_PITCH + k0 + 8];
        unsigned a3 = *(const unsigned*)&Xs[(mbase + gid + 8) * XS_PITCH + k0 + 8];
        #pragma unroll
        for (int nt = 0; nt < 8; nt++) {
            unsigned b0 = *(const unsigned*)&Wt[(nt * 8 + gid) * XS_PITCH + k0];
            unsigned b1 = *(const unsigned*)&Wt[(nt * 8 + gid) * XS_PITCH + k0 + 8];
            asm volatile(
                "mma.sync.aligned.m16n8k16.row.col.f32.f16.f16.f32 "
                "{%0,%1,%2,%3}, {%4,%5,%6,%7}, {%8,%9}, {%0,%1,%2,%3};"
                : "+f"(c[nt][0]), "+f"(c[nt][1]), "+f"(c[nt][2]), "+f"(c[nt][3])
                : "r"(a0), "r"(a1), "r"(a2), "r"(a3), "r"(b0), "r"(b1));
        }
    }

    // epilogue: +bias (, relu*dinv); c0,c1 = row gid, c2,c3 = row gid+8
    int node = base + mbase + gid;
    float di0 = (RELU && node < n) ? d_dinv[node] : 0.f;
    float di8 = (RELU && node + 8 < n) ? d_dinv[node + 8] : 0.f;
    #pragma unroll
    for (int nt = 0; nt < 8; nt++) {
        int word = nt * 4 + tig;  // half2/float2 word = features {2w, 2w+1}
        float2 bb = __ldg(&((const float2*)bias)[word]);
        float v0 = c[nt][0] + bb.x, v1 = c[nt][1] + bb.y;
        float v2 = c[nt][2] + bb.x, v3 = c[nt][3] + bb.y;
        if (RELU) {
            v0 = fmaxf(v0, 0.f) * di0; v1 = fmaxf(v1, 0.f) * di0;
            v2 = fmaxf(v2, 0.f) * di8; v3 = fmaxf(v3, 0.f) * di8;
            if (node < n)
                d_gh[node * 32 + word] = h2_bits(__floats2half2_rn(v0, v1));
            if (node + 8 < n)
                d_gh[(node + 8) * 32 + word] = h2_bits(__floats2half2_rn(v2, v3));
        } else {
            if (node < n)
                ((float2*)OUT)[node * 32 + word] = make_float2(v0, v1);
            if (node + 8 < n)
                ((float2*)OUT)[(node + 8) * 32 + word] = make_float2(v2, v3);
        }
    }
}

// ---------------- launch -----------------------------------------------------
extern "C" void kernel_launch(void* const* d_in, const int* in_sizes, int n_in,
                              void* d_out, int out_size) {
    const float* x = (const float*)d_in[0];
    const void* ei = d_in[1];
    const float* W1 = (const float*)d_in[2];
    const float* b1 = (const float*)d_in[3];
    const float* W2 = (const float*)d_in[4];
    const float* b2 = (const float*)d_in[5];
    float* out = (float*)d_out;

    int N = in_sizes[0] / F;          // 100000
    int E = in_sizes[1] / 2;          // 1600000
    int nbS = (N + 511) / 512;        // 196 scan blocks
    int Eh = (E + 1) / 2;
    int nbH = (Eh + 255) / 256;       // hist blocks (2 edges/thread)
    int nbSc = (Eh + N + 255) / 256;  // scatter blocks
    int nbX = (N * 16 + 255) / 256;   // xh blocks

    // graph build; fused scatter+xh at profiled slot 4
    k_init<<<(N + 255) / 256, 256>>>((const unsigned int*)ei, N);
    k_hist<<<nbH, 256>>>(ei, E);
    k_scan<<<nbS, 512>>>(N, nbS, E + N);
    k_scatxh<<<nbSc + nbX, 256>>>(ei, x, E, N, nbSc, N * 16);  // profiled slot

    // layer 1: AX = dinv*agg(xh); gh = dinv*relu(AX@W1 + b1)
    k_agg<false><<<(N * 32 + 255) / 256, 256>>>(N);
    k_gemm<true><<<(N + 127) / 128, 256>>>(W1, b1, out /*unused*/, N);

    // layer 2: Ag = dinv*agg(gh); out = Ag@W2 + b2
    k_agg<true><<<(N * 32 + 255) / 256, 256>>>(N);
    k_gemm<false><<<(N + 127) / 128, 256>>>(W2, b2, out, N);
}